// round 7
// baseline (speedup 1.0000x reference)
#include <cuda_runtime.h>

// Fixed problem shapes (SpanRepresentation_32487132627590)
#define BATCH   4
#define SLEN    2048
#define DIM     768
#define DIM4    (DIM / 4)               // 192
#define NSPAN   4096
#define NROWS   (BATCH * NSPAN)         // 16384
#define CHUNK   64
#define NCHUNK  (SLEN / CHUNK)          // 32
#define NCBLK   (BATCH * NCHUNK)        // 128 cumsum blocks
#define HALF    (NROWS / 2)             // 8192
#define OUTW    2364
#define OFF_MEAN 0
#define OFF_XS0  768
#define OFF_P0   1536
#define OFF_XS1  1556
#define OFF_P1   2324
#define OFF_W    2344

// exclusive prefix sums cs[b, s, d], s in [0, SLEN]  (~25.2 MB)
__device__ float g_cs[(size_t)BATCH * (SLEN + 1) * DIM];
// per-chunk sums
__device__ float g_chunk[(size_t)BATCH * NCHUNK * DIM];

static __device__ __forceinline__ float4 f4add(float4 a, float4 b) {
    a.x += b.x; a.y += b.y; a.z += b.z; a.w += b.w; return a;
}

// ---------------------------------------------------------------------------
// span_rest: xs0, pos0, xs1, pos1, width segments for output row bn
// ---------------------------------------------------------------------------
static __device__ __forceinline__
void span_rest_body(int bn, int t,
                    const float* __restrict__ x,
                    const int* __restrict__ spans,
                    const int* __restrict__ pt_labels,
                    const float* __restrict__ wtab,
                    const float* __restrict__ ptab,
                    float* __restrict__ out) {
    const int b = bn >> 12;
    const int n = bn & (NSPAN - 1);

    const int i0 = spans[2 * n + 0];
    const int i1 = spans[2 * n + 1];
    const int width = i1 - i0 + 1;

    const int bins[16] = {0,1,2,3,4,5,7,8,9,10,15,16,31,32,63,64};
    int em = 0;
    #pragma unroll
    for (int i = 1; i < 16; i++) em = (width >= bins[i]) ? i : em;

    const int l0 = pt_labels[i0];
    const int l1 = pt_labels[i1];

    const float4 v0 = ((const float4*)(x + ((size_t)b * SLEN + i0) * DIM))[t];
    const float4 v1 = ((const float4*)(x + ((size_t)b * SLEN + i1) * DIM))[t];
    float* orow = out + (size_t)bn * OUTW;

    ((float4*)(orow + OFF_XS0))[t] = v0;
    ((float4*)(orow + OFF_XS1))[t] = v1;

    if (t < 5) {
        ((float4*)(orow + OFF_P0))[t] = ((const float4*)(ptab + l0 * 20))[t];
        ((float4*)(orow + OFF_P1))[t] = ((const float4*)(ptab + l1 * 20))[t];
        ((float4*)(orow + OFF_W ))[t] = ((const float4*)(wtab + em * 20))[t];
    }
}

// ---------------------------------------------------------------------------
// fusedA: blocks [0,128) chunksum; blocks [128, 128+8192) span_rest
// ---------------------------------------------------------------------------
__global__ __launch_bounds__(DIM4)
void fusedA_kernel(const float* __restrict__ x,
                   const int* __restrict__ spans,
                   const int* __restrict__ pt_labels,
                   const float* __restrict__ wtab,
                   const float* __restrict__ ptab,
                   float* __restrict__ out) {
    const int t = threadIdx.x;
    if (blockIdx.x < NCBLK) {
        const int bc = blockIdx.x;
        const float4* p = (const float4*)(x + (size_t)bc * CHUNK * DIM) + t;
        float4 a0 = p[0*DIM4], a1 = p[1*DIM4], a2 = p[2*DIM4], a3 = p[3*DIM4];
        float4 a4 = p[4*DIM4], a5 = p[5*DIM4], a6 = p[6*DIM4], a7 = p[7*DIM4];
        #pragma unroll
        for (int i = 8; i < CHUNK; i += 8) {
            a0 = f4add(a0, p[(i+0)*DIM4]);
            a1 = f4add(a1, p[(i+1)*DIM4]);
            a2 = f4add(a2, p[(i+2)*DIM4]);
            a3 = f4add(a3, p[(i+3)*DIM4]);
            a4 = f4add(a4, p[(i+4)*DIM4]);
            a5 = f4add(a5, p[(i+5)*DIM4]);
            a6 = f4add(a6, p[(i+6)*DIM4]);
            a7 = f4add(a7, p[(i+7)*DIM4]);
        }
        float4 s = f4add(f4add(f4add(a0,a1), f4add(a2,a3)),
                         f4add(f4add(a4,a5), f4add(a6,a7)));
        ((float4*)(g_chunk + (size_t)bc * DIM))[t] = s;
    } else {
        span_rest_body(blockIdx.x - NCBLK, t, x, spans, pt_labels, wtab, ptab, out);
    }
}

// ---------------------------------------------------------------------------
// fusedB: blocks [0,128) scan->cs; blocks [128, 128+8192) span_rest
// ---------------------------------------------------------------------------
__global__ __launch_bounds__(DIM4)
void fusedB_kernel(const float* __restrict__ x,
                   const int* __restrict__ spans,
                   const int* __restrict__ pt_labels,
                   const float* __restrict__ wtab,
                   const float* __restrict__ ptab,
                   float* __restrict__ out) {
    const int t = threadIdx.x;
    if (blockIdx.x < NCBLK) {
        const int bc = blockIdx.x;
        const int b  = bc / NCHUNK;
        const int c  = bc % NCHUNK;

        // exclusive prefix of chunk sums: fully unrolled, predicated ->
        // 32 independent (mostly L2-hit) loads, pipelined, no serial chain
        float4 run = make_float4(0.f, 0.f, 0.f, 0.f);
        const float4* ch = (const float4*)(g_chunk + (size_t)b * NCHUNK * DIM) + t;
        #pragma unroll
        for (int cc = 0; cc < NCHUNK; cc++) {
            if (cc < c) run = f4add(run, ch[(size_t)cc * DIM4]);
        }

        const float4* p = (const float4*)(x    + ((size_t)b * SLEN       + (size_t)c * CHUNK) * DIM) + t;
        float4*       q = (float4*)      (g_cs + ((size_t)b * (SLEN + 1) + (size_t)c * CHUNK) * DIM) + t;

        #pragma unroll 4
        for (int i = 0; i < CHUNK; i++) {
            q[(size_t)i * DIM4] = run;
            run = f4add(run, p[(size_t)i * DIM4]);
        }
        if (c == NCHUNK - 1) q[CHUNK * DIM4] = run;   // cs[SLEN]
    } else {
        span_rest_body(HALF + (blockIdx.x - NCBLK), t, x, spans, pt_labels, wtab, ptab, out);
    }
}

// ---------------------------------------------------------------------------
// span_mean: mean segment only.  grid = 16384, block = 192
// ---------------------------------------------------------------------------
__global__ __launch_bounds__(DIM4)
void span_mean_kernel(const int* __restrict__ spans,
                      float* __restrict__ out) {
    const int bn = blockIdx.x;
    const int b  = bn >> 12;
    const int n  = bn & (NSPAN - 1);
    const int t  = threadIdx.x;

    const int i0 = spans[2 * n + 0];
    const int i1 = spans[2 * n + 1];
    const float inv_w = 1.0f / (float)(i1 - i0 + 1);

    const float4 a  = ((const float4*)(g_cs + ((size_t)b * (SLEN + 1) + i0    ) * DIM))[t];
    const float4 bb = ((const float4*)(g_cs + ((size_t)b * (SLEN + 1) + i1 + 1) * DIM))[t];

    float4 m;
    m.x = (bb.x - a.x) * inv_w;
    m.y = (bb.y - a.y) * inv_w;
    m.z = (bb.z - a.z) * inv_w;
    m.w = (bb.w - a.w) * inv_w;
    ((float4*)(out + (size_t)bn * OUTW + OFF_MEAN))[t] = m;
}

// ---------------------------------------------------------------------------
extern "C" void kernel_launch(void* const* d_in, const int* in_sizes, int n_in,
                              void* d_out, int out_size) {
    const float* x      = (const float*)d_in[0];
    const int*   spans  = (const int*)d_in[1];
    const int*   labels = (const int*)d_in[2];
    const float* wtab   = (const float*)d_in[3];
    const float* ptab   = (const float*)d_in[4];
    float*       out    = (float*)d_out;

    fusedA_kernel   <<<NCBLK + HALF, DIM4>>>(x, spans, labels, wtab, ptab, out);
    fusedB_kernel   <<<NCBLK + HALF, DIM4>>>(x, spans, labels, wtab, ptab, out);
    span_mean_kernel<<<NROWS, DIM4>>>(spans, out);
}

// round 8
// speedup vs baseline: 1.0016x; 1.0016x over previous
#include <cuda_runtime.h>

// Fixed problem shapes (SpanRepresentation_32487132627590)
#define BATCH   4
#define SLEN    2048
#define DIM     768
#define DIM4    (DIM / 4)               // 192
#define NSPAN   4096
#define NROWS   (BATCH * NSPAN)         // 16384
#define CHUNK   64
#define NCHUNK  (SLEN / CHUNK)          // 32
#define NCBLK   (BATCH * NCHUNK)        // 128 cumsum blocks
#define HALF    (NROWS / 2)             // 8192
#define OUTW    2364
#define OFF_MEAN 0
#define OFF_XS0  768
#define OFF_P0   1536
#define OFF_XS1  1556
#define OFF_P1   2324
#define OFF_W    2344

// exclusive prefix sums cs[b, s, d], s in [0, SLEN]  (~25.2 MB)
__device__ float g_cs[(size_t)BATCH * (SLEN + 1) * DIM];
// per-chunk sums
__device__ float g_chunk[(size_t)BATCH * NCHUNK * DIM];

static __device__ __forceinline__ float4 f4add(float4 a, float4 b) {
    a.x += b.x; a.y += b.y; a.z += b.z; a.w += b.w; return a;
}

// ---------------------------------------------------------------------------
// span_rest: xs0, pos0, xs1, pos1, width segments for output row bn
// ---------------------------------------------------------------------------
static __device__ __forceinline__
void span_rest_body(int bn, int t,
                    const float* __restrict__ x,
                    const int* __restrict__ spans,
                    const int* __restrict__ pt_labels,
                    const float* __restrict__ wtab,
                    const float* __restrict__ ptab,
                    float* __restrict__ out) {
    const int b = bn >> 12;
    const int n = bn & (NSPAN - 1);

    const int i0 = spans[2 * n + 0];
    const int i1 = spans[2 * n + 1];
    const int width = i1 - i0 + 1;

    const int bins[16] = {0,1,2,3,4,5,7,8,9,10,15,16,31,32,63,64};
    int em = 0;
    #pragma unroll
    for (int i = 1; i < 16; i++) em = (width >= bins[i]) ? i : em;

    const int l0 = pt_labels[i0];
    const int l1 = pt_labels[i1];

    const float4 v0 = ((const float4*)(x + ((size_t)b * SLEN + i0) * DIM))[t];
    const float4 v1 = ((const float4*)(x + ((size_t)b * SLEN + i1) * DIM))[t];
    float* orow = out + (size_t)bn * OUTW;

    ((float4*)(orow + OFF_XS0))[t] = v0;
    ((float4*)(orow + OFF_XS1))[t] = v1;

    if (t < 5) {
        ((float4*)(orow + OFF_P0))[t] = ((const float4*)(ptab + l0 * 20))[t];
        ((float4*)(orow + OFF_P1))[t] = ((const float4*)(ptab + l1 * 20))[t];
        ((float4*)(orow + OFF_W ))[t] = ((const float4*)(wtab + em * 20))[t];
    }
}

// ---------------------------------------------------------------------------
// fusedA: blocks [0,128) chunksum; blocks [128, 128+8192) span_rest
// ---------------------------------------------------------------------------
__global__ __launch_bounds__(DIM4)
void fusedA_kernel(const float* __restrict__ x,
                   const int* __restrict__ spans,
                   const int* __restrict__ pt_labels,
                   const float* __restrict__ wtab,
                   const float* __restrict__ ptab,
                   float* __restrict__ out) {
    const int t = threadIdx.x;
    if (blockIdx.x < NCBLK) {
        const int bc = blockIdx.x;
        const float4* p = (const float4*)(x + (size_t)bc * CHUNK * DIM) + t;
        float4 a0 = p[0*DIM4], a1 = p[1*DIM4], a2 = p[2*DIM4], a3 = p[3*DIM4];
        float4 a4 = p[4*DIM4], a5 = p[5*DIM4], a6 = p[6*DIM4], a7 = p[7*DIM4];
        #pragma unroll
        for (int i = 8; i < CHUNK; i += 8) {
            a0 = f4add(a0, p[(i+0)*DIM4]);
            a1 = f4add(a1, p[(i+1)*DIM4]);
            a2 = f4add(a2, p[(i+2)*DIM4]);
            a3 = f4add(a3, p[(i+3)*DIM4]);
            a4 = f4add(a4, p[(i+4)*DIM4]);
            a5 = f4add(a5, p[(i+5)*DIM4]);
            a6 = f4add(a6, p[(i+6)*DIM4]);
            a7 = f4add(a7, p[(i+7)*DIM4]);
        }
        float4 s = f4add(f4add(f4add(a0,a1), f4add(a2,a3)),
                         f4add(f4add(a4,a5), f4add(a6,a7)));
        ((float4*)(g_chunk + (size_t)bc * DIM))[t] = s;
    } else {
        span_rest_body(blockIdx.x - NCBLK, t, x, spans, pt_labels, wtab, ptab, out);
    }
}

// ---------------------------------------------------------------------------
// fusedB: blocks [0,128) scan->cs; blocks [128, 128+8192) span_rest
// ---------------------------------------------------------------------------
__global__ __launch_bounds__(DIM4)
void fusedB_kernel(const float* __restrict__ x,
                   const int* __restrict__ spans,
                   const int* __restrict__ pt_labels,
                   const float* __restrict__ wtab,
                   const float* __restrict__ ptab,
                   float* __restrict__ out) {
    const int t = threadIdx.x;
    if (blockIdx.x < NCBLK) {
        const int bc = blockIdx.x;
        const int b  = bc / NCHUNK;
        const int c  = bc % NCHUNK;

        // exclusive prefix of chunk sums: fully unrolled, predicated ->
        // 32 independent (mostly L2-hit) loads, pipelined, no serial chain
        float4 run = make_float4(0.f, 0.f, 0.f, 0.f);
        const float4* ch = (const float4*)(g_chunk + (size_t)b * NCHUNK * DIM) + t;
        #pragma unroll
        for (int cc = 0; cc < NCHUNK; cc++) {
            if (cc < c) run = f4add(run, ch[(size_t)cc * DIM4]);
        }

        const float4* p = (const float4*)(x    + ((size_t)b * SLEN       + (size_t)c * CHUNK) * DIM) + t;
        float4*       q = (float4*)      (g_cs + ((size_t)b * (SLEN + 1) + (size_t)c * CHUNK) * DIM) + t;

        #pragma unroll 4
        for (int i = 0; i < CHUNK; i++) {
            q[(size_t)i * DIM4] = run;
            run = f4add(run, p[(size_t)i * DIM4]);
        }
        if (c == NCHUNK - 1) q[CHUNK * DIM4] = run;   // cs[SLEN]
    } else {
        span_rest_body(HALF + (blockIdx.x - NCBLK), t, x, spans, pt_labels, wtab, ptab, out);
    }
}

// ---------------------------------------------------------------------------
// span_mean: mean segment only.  grid = 16384, block = 192
// ---------------------------------------------------------------------------
__global__ __launch_bounds__(DIM4)
void span_mean_kernel(const int* __restrict__ spans,
                      float* __restrict__ out) {
    const int bn = blockIdx.x;
    const int b  = bn >> 12;
    const int n  = bn & (NSPAN - 1);
    const int t  = threadIdx.x;

    const int i0 = spans[2 * n + 0];
    const int i1 = spans[2 * n + 1];
    const float inv_w = 1.0f / (float)(i1 - i0 + 1);

    const float4 a  = ((const float4*)(g_cs + ((size_t)b * (SLEN + 1) + i0    ) * DIM))[t];
    const float4 bb = ((const float4*)(g_cs + ((size_t)b * (SLEN + 1) + i1 + 1) * DIM))[t];

    float4 m;
    m.x = (bb.x - a.x) * inv_w;
    m.y = (bb.y - a.y) * inv_w;
    m.z = (bb.z - a.z) * inv_w;
    m.w = (bb.w - a.w) * inv_w;
    ((float4*)(out + (size_t)bn * OUTW + OFF_MEAN))[t] = m;
}

// ---------------------------------------------------------------------------
extern "C" void kernel_launch(void* const* d_in, const int* in_sizes, int n_in,
                              void* d_out, int out_size) {
    const float* x      = (const float*)d_in[0];
    const int*   spans  = (const int*)d_in[1];
    const int*   labels = (const int*)d_in[2];
    const float* wtab   = (const float*)d_in[3];
    const float* ptab   = (const float*)d_in[4];
    float*       out    = (float*)d_out;

    fusedA_kernel   <<<NCBLK + HALF, DIM4>>>(x, spans, labels, wtab, ptab, out);
    fusedB_kernel   <<<NCBLK + HALF, DIM4>>>(x, spans, labels, wtab, ptab, out);
    span_mean_kernel<<<NROWS, DIM4>>>(spans, out);
}

// round 9
// speedup vs baseline: 1.0207x; 1.0191x over previous
#include <cuda_runtime.h>

// Fixed problem shapes (SpanRepresentation_32487132627590)
#define BATCH   4
#define SLEN    2048
#define DIM     768
#define DIM4    (DIM / 4)               // 192
#define NSPAN   4096
#define NROWS   (BATCH * NSPAN)         // 16384
#define CHUNK   64
#define NCHUNK  (SLEN / CHUNK)          // 32
#define NCBLK   (BATCH * NCHUNK)        // 128
#define OUTW    2364
#define OFF_MEAN 0
#define OFF_XS0  768
#define OFF_P0   1536
#define OFF_XS1  1556
#define OFF_P1   2324
#define OFF_W    2344

// exclusive prefix sums cs[b, s, d], s in [0, SLEN]  (~25.2 MB)
__device__ float g_cs[(size_t)BATCH * (SLEN + 1) * DIM];
// per-chunk sums
__device__ float g_chunk[(size_t)BATCH * NCHUNK * DIM];

// ---------------------------------------------------------------------------
// chunksum (R2-proven): grid = 128, block = 768
// ---------------------------------------------------------------------------
__global__ __launch_bounds__(DIM)
void chunksum_kernel(const float* __restrict__ x) {
    const int d  = threadIdx.x;
    const int bc = blockIdx.x;
    const float* p = x + (size_t)bc * CHUNK * DIM + d;

    float a0 = 0.f, a1 = 0.f, a2 = 0.f, a3 = 0.f;
    #pragma unroll
    for (int i = 0; i < CHUNK; i += 4) {
        a0 += p[(size_t)(i + 0) * DIM];
        a1 += p[(size_t)(i + 1) * DIM];
        a2 += p[(size_t)(i + 2) * DIM];
        a3 += p[(size_t)(i + 3) * DIM];
    }
    g_chunk[(size_t)bc * DIM + d] = (a0 + a1) + (a2 + a3);
}

// ---------------------------------------------------------------------------
// scan (R2-proven): grid = 128, block = 768
// ---------------------------------------------------------------------------
__global__ __launch_bounds__(DIM)
void scan_write_kernel(const float* __restrict__ x) {
    const int d  = threadIdx.x;
    const int bc = blockIdx.x;
    const int b  = bc / NCHUNK;
    const int c  = bc % NCHUNK;

    float run = 0.f;
    const float* ch = g_chunk + (size_t)b * NCHUNK * DIM + d;
    for (int cc = 0; cc < c; cc++) run += ch[(size_t)cc * DIM];

    const float* p = x    + ((size_t)b * SLEN       + (size_t)c * CHUNK) * DIM + d;
    float*       q = g_cs + ((size_t)b * (SLEN + 1) + (size_t)c * CHUNK) * DIM + d;

    #pragma unroll 4
    for (int i = 0; i < CHUNK; i++) {
        q[(size_t)i * DIM] = run;
        run += p[(size_t)i * DIM];
    }
    if (c == NCHUNK - 1) q[(size_t)CHUNK * DIM] = run;
}

// ---------------------------------------------------------------------------
// span_rest: xs0/pos0/xs1/pos1/width for every row.  grid = 16384, block=192
// (independent of cs -> runs concurrently with the cumsum branch)
// ---------------------------------------------------------------------------
__global__ __launch_bounds__(DIM4)
void span_rest_kernel(const float* __restrict__ x,
                      const int* __restrict__ spans,
                      const int* __restrict__ pt_labels,
                      const float* __restrict__ wtab,
                      const float* __restrict__ ptab,
                      float* __restrict__ out) {
    const int bn = blockIdx.x;
    const int b  = bn >> 12;
    const int n  = bn & (NSPAN - 1);
    const int t  = threadIdx.x;

    const int i0 = spans[2 * n + 0];
    const int i1 = spans[2 * n + 1];
    const int width = i1 - i0 + 1;

    const int bins[16] = {0,1,2,3,4,5,7,8,9,10,15,16,31,32,63,64};
    int em = 0;
    #pragma unroll
    for (int i = 1; i < 16; i++) em = (width >= bins[i]) ? i : em;

    const int l0 = pt_labels[i0];
    const int l1 = pt_labels[i1];

    const float4 v0 = ((const float4*)(x + ((size_t)b * SLEN + i0) * DIM))[t];
    const float4 v1 = ((const float4*)(x + ((size_t)b * SLEN + i1) * DIM))[t];
    float* orow = out + (size_t)bn * OUTW;

    ((float4*)(orow + OFF_XS0))[t] = v0;
    ((float4*)(orow + OFF_XS1))[t] = v1;

    if (t < 5) {
        ((float4*)(orow + OFF_P0))[t] = ((const float4*)(ptab + l0 * 20))[t];
        ((float4*)(orow + OFF_P1))[t] = ((const float4*)(ptab + l1 * 20))[t];
        ((float4*)(orow + OFF_W ))[t] = ((const float4*)(wtab + em * 20))[t];
    }
}

// ---------------------------------------------------------------------------
// span_mean: mean segment (needs cs).  grid = 16384, block = 192
// ---------------------------------------------------------------------------
__global__ __launch_bounds__(DIM4)
void span_mean_kernel(const int* __restrict__ spans,
                      float* __restrict__ out) {
    const int bn = blockIdx.x;
    const int b  = bn >> 12;
    const int n  = bn & (NSPAN - 1);
    const int t  = threadIdx.x;

    const int i0 = spans[2 * n + 0];
    const int i1 = spans[2 * n + 1];
    const float inv_w = 1.0f / (float)(i1 - i0 + 1);

    const float4 a  = ((const float4*)(g_cs + ((size_t)b * (SLEN + 1) + i0    ) * DIM))[t];
    const float4 bb = ((const float4*)(g_cs + ((size_t)b * (SLEN + 1) + i1 + 1) * DIM))[t];

    float4 m;
    m.x = (bb.x - a.x) * inv_w;
    m.y = (bb.y - a.y) * inv_w;
    m.z = (bb.z - a.z) * inv_w;
    m.w = (bb.w - a.w) * inv_w;
    ((float4*)(out + (size_t)bn * OUTW + OFF_MEAN))[t] = m;
}

// ---------------------------------------------------------------------------
extern "C" void kernel_launch(void* const* d_in, const int* in_sizes, int n_in,
                              void* d_out, int out_size) {
    const float* x      = (const float*)d_in[0];
    const int*   spans  = (const int*)d_in[1];
    const int*   labels = (const int*)d_in[2];
    const float* wtab   = (const float*)d_in[3];
    const float* ptab   = (const float*)d_in[4];
    float*       out    = (float*)d_out;

    // One-time handle creation (no device memory; identical work every call).
    static cudaStream_t s2 = nullptr;
    static cudaEvent_t  eFork = nullptr, eJoin = nullptr;
    if (s2 == nullptr) {
        cudaStreamCreateWithFlags(&s2, cudaStreamNonBlocking);
        cudaEventCreateWithFlags(&eFork, cudaEventDisableTiming);
        cudaEventCreateWithFlags(&eJoin, cudaEventDisableTiming);
    }

    // Fork: side stream runs the cumsum chain while the main (capture) stream
    // streams out the cs-independent output segments.
    cudaEventRecord(eFork, 0);
    cudaStreamWaitEvent(s2, eFork, 0);

    chunksum_kernel  <<<NCBLK, DIM, 0, s2>>>(x);
    scan_write_kernel<<<NCBLK, DIM, 0, s2>>>(x);
    cudaEventRecord(eJoin, s2);

    span_rest_kernel <<<NROWS, DIM4>>>(x, spans, labels, wtab, ptab, out);

    // Join, then the cs-dependent mean segment.
    cudaStreamWaitEvent(0, eJoin, 0);
    span_mean_kernel <<<NROWS, DIM4>>>(spans, out);
}

// round 10
// speedup vs baseline: 1.2520x; 1.2266x over previous
#include <cuda_runtime.h>

// Fixed problem shapes (SpanRepresentation_32487132627590)
#define BATCH   4
#define SLEN    2048
#define DIM     768
#define DIM4    (DIM / 4)               // 192
#define NSPAN   4096
#define NROWS   (BATCH * NSPAN)         // 16384
#define CHUNK   64
#define NCHUNK  (SLEN / CHUNK)          // 32
#define NCBLK   (BATCH * NCHUNK)        // 128
#define OUTW    2364
#define OFF_MEAN 0
#define OFF_XS0  768
#define OFF_P0   1536
#define OFF_XS1  1556
#define OFF_P1   2324
#define OFF_W    2344

// exclusive prefix sums cs[b, s, d], s in [0, SLEN]  (~25.2 MB)
__device__ float g_cs[(size_t)BATCH * (SLEN + 1) * DIM];
// per-chunk sums and their exclusive prefixes
__device__ float g_chunk[(size_t)BATCH * NCHUNK * DIM];
__device__ float g_pref [(size_t)BATCH * NCHUNK * DIM];

// ---------------------------------------------------------------------------
// Kernel 1 (R2-proven): per-chunk partial sums.  grid = 128, block = 768
// ---------------------------------------------------------------------------
__global__ __launch_bounds__(DIM)
void chunksum_kernel(const float* __restrict__ x) {
    const int d  = threadIdx.x;
    const int bc = blockIdx.x;
    const float* p = x + (size_t)bc * CHUNK * DIM + d;

    float a0 = 0.f, a1 = 0.f, a2 = 0.f, a3 = 0.f;
    #pragma unroll
    for (int i = 0; i < CHUNK; i += 4) {
        a0 += p[(size_t)(i + 0) * DIM];
        a1 += p[(size_t)(i + 1) * DIM];
        a2 += p[(size_t)(i + 2) * DIM];
        a3 += p[(size_t)(i + 3) * DIM];
    }
    g_chunk[(size_t)bc * DIM + d] = (a0 + a1) + (a2 + a3);
}

// ---------------------------------------------------------------------------
// Kernel 2: exclusive scan of the 32 chunk sums per (b, d).
// grid = BATCH (4), block = 768.  Data is tiny (384 KB) and L2-hot.
// ---------------------------------------------------------------------------
__global__ __launch_bounds__(DIM)
void chunk_prefix_kernel() {
    const int d = threadIdx.x;
    const int b = blockIdx.x;
    const float* ch = g_chunk + (size_t)b * NCHUNK * DIM + d;
    float*       pf = g_pref  + (size_t)b * NCHUNK * DIM + d;

    // preload all 32 values (independent loads, pipelined)
    float v[NCHUNK];
    #pragma unroll
    for (int c = 0; c < NCHUNK; c++) v[c] = ch[(size_t)c * DIM];

    float run = 0.f;
    #pragma unroll
    for (int c = 0; c < NCHUNK; c++) {
        pf[(size_t)c * DIM] = run;
        run += v[c];
    }
}

// ---------------------------------------------------------------------------
// Kernel 3: pure streaming scan -> cs (no lookback loop).
// grid = 128, block = 768
// ---------------------------------------------------------------------------
__global__ __launch_bounds__(DIM)
void scan_write_kernel(const float* __restrict__ x) {
    const int d  = threadIdx.x;
    const int bc = blockIdx.x;
    const int b  = bc / NCHUNK;
    const int c  = bc % NCHUNK;

    float run = g_pref[(size_t)bc * DIM + d];   // exclusive chunk prefix

    const float* p = x    + ((size_t)b * SLEN       + (size_t)c * CHUNK) * DIM + d;
    float*       q = g_cs + ((size_t)b * (SLEN + 1) + (size_t)c * CHUNK) * DIM + d;

    #pragma unroll 4
    for (int i = 0; i < CHUNK; i++) {
        q[(size_t)i * DIM] = run;
        run += p[(size_t)i * DIM];
    }
    if (c == NCHUNK - 1) q[(size_t)CHUNK * DIM] = run;   // cs[SLEN]
}

// ---------------------------------------------------------------------------
// Kernel 4 (R2 skeleton + streaming stores): one block per output row.
// grid = 16384, block = 192
// ---------------------------------------------------------------------------
__global__ __launch_bounds__(DIM4)
void span_kernel(const float* __restrict__ x,
                 const int* __restrict__ spans,
                 const int* __restrict__ pt_labels,
                 const float* __restrict__ wtab,
                 const float* __restrict__ ptab,
                 float* __restrict__ out) {
    const int bn = blockIdx.x;
    const int b  = bn >> 12;
    const int n  = bn & (NSPAN - 1);
    const int t  = threadIdx.x;

    const int i0 = spans[2 * n + 0];
    const int i1 = spans[2 * n + 1];
    const int width = i1 - i0 + 1;

    const int bins[16] = {0,1,2,3,4,5,7,8,9,10,15,16,31,32,63,64};
    int em = 0;
    #pragma unroll
    for (int i = 1; i < 16; i++) em = (width >= bins[i]) ? i : em;

    const int l0 = pt_labels[i0];
    const int l1 = pt_labels[i1];
    const float inv_w = 1.0f / (float)width;

    const float4 a  = ((const float4*)(g_cs + ((size_t)b * (SLEN + 1) + i0    ) * DIM))[t];
    const float4 bb = ((const float4*)(g_cs + ((size_t)b * (SLEN + 1) + i1 + 1) * DIM))[t];
    const float4 v0 = ((const float4*)(x    + ((size_t)b * SLEN + i0) * DIM))[t];
    const float4 v1 = ((const float4*)(x    + ((size_t)b * SLEN + i1) * DIM))[t];
    float* orow = out + (size_t)bn * OUTW;

    float4 m;
    m.x = (bb.x - a.x) * inv_w;
    m.y = (bb.y - a.y) * inv_w;
    m.z = (bb.z - a.z) * inv_w;
    m.w = (bb.w - a.w) * inv_w;

    // streaming stores: don't let the 155MB output stream evict x/cs from L2
    __stcs((float4*)(orow + OFF_MEAN) + t, m);
    __stcs((float4*)(orow + OFF_XS0 ) + t, v0);
    __stcs((float4*)(orow + OFF_XS1 ) + t, v1);

    if (t < 5) {
        ((float4*)(orow + OFF_P0))[t] = ((const float4*)(ptab + l0 * 20))[t];
        ((float4*)(orow + OFF_P1))[t] = ((const float4*)(ptab + l1 * 20))[t];
        ((float4*)(orow + OFF_W ))[t] = ((const float4*)(wtab + em * 20))[t];
    }
}

// ---------------------------------------------------------------------------
extern "C" void kernel_launch(void* const* d_in, const int* in_sizes, int n_in,
                              void* d_out, int out_size) {
    const float* x      = (const float*)d_in[0];
    const int*   spans  = (const int*)d_in[1];
    const int*   labels = (const int*)d_in[2];
    const float* wtab   = (const float*)d_in[3];
    const float* ptab   = (const float*)d_in[4];
    float*       out    = (float*)d_out;

    chunksum_kernel    <<<NCBLK, DIM>>>(x);
    chunk_prefix_kernel<<<BATCH, DIM>>>();
    scan_write_kernel  <<<NCBLK, DIM>>>(x);
    span_kernel        <<<NROWS, DIM4>>>(x, spans, labels, wtab, ptab, out);
}

// round 11
// speedup vs baseline: 1.2587x; 1.0054x over previous
#include <cuda_runtime.h>

// Fixed problem shapes (SpanRepresentation_32487132627590)
#define BATCH   4
#define SLEN    2048
#define DIM     768
#define DIM4    (DIM / 4)               // 192
#define NSPAN   4096
#define NROWS   (BATCH * NSPAN)         // 16384
#define CHUNK   64
#define NCHUNK  (SLEN / CHUNK)          // 32
#define NCBLK   (BATCH * NCHUNK)        // 128
#define OUTW    2364
#define OFF_MEAN 0
#define OFF_XS0  768
#define OFF_P0   1536
#define OFF_XS1  1556
#define OFF_P1   2324
#define OFF_W    2344

// exclusive prefix sums cs[b, s, d], s in [0, SLEN]  (~25.2 MB)
__device__ float g_cs[(size_t)BATCH * (SLEN + 1) * DIM];
// per-chunk sums
__device__ float g_chunk[(size_t)BATCH * NCHUNK * DIM];

// ---------------------------------------------------------------------------
// Kernel 1 (proven): per-chunk partial sums.  grid = 128, block = 768
// ---------------------------------------------------------------------------
__global__ __launch_bounds__(DIM)
void chunksum_kernel(const float* __restrict__ x) {
    const int d  = threadIdx.x;
    const int bc = blockIdx.x;
    const float* p = x + (size_t)bc * CHUNK * DIM + d;

    float a0 = 0.f, a1 = 0.f, a2 = 0.f, a3 = 0.f;
    #pragma unroll
    for (int i = 0; i < CHUNK; i += 4) {
        a0 += p[(size_t)(i + 0) * DIM];
        a1 += p[(size_t)(i + 1) * DIM];
        a2 += p[(size_t)(i + 2) * DIM];
        a3 += p[(size_t)(i + 3) * DIM];
    }
    g_chunk[(size_t)bc * DIM + d] = (a0 + a1) + (a2 + a3);
}

// ---------------------------------------------------------------------------
// Kernel 2: scan -> cs, with inline chunk-prefix (unrolled, predicated:
// 32 independent L2-hot loads, no serial lookback).  grid = 128, block = 768
// ---------------------------------------------------------------------------
__global__ __launch_bounds__(DIM)
void scan_write_kernel(const float* __restrict__ x) {
    const int d  = threadIdx.x;
    const int bc = blockIdx.x;
    const int b  = bc / NCHUNK;
    const int c  = bc % NCHUNK;

    // exclusive prefix of chunk sums (g_chunk is tiny and L2-resident)
    const float* ch = g_chunk + (size_t)b * NCHUNK * DIM + d;
    float run = 0.f;
    #pragma unroll
    for (int cc = 0; cc < NCHUNK; cc++) {
        float v = (cc < c) ? ch[(size_t)cc * DIM] : 0.f;
        run += v;
    }

    const float* p = x    + ((size_t)b * SLEN       + (size_t)c * CHUNK) * DIM + d;
    float*       q = g_cs + ((size_t)b * (SLEN + 1) + (size_t)c * CHUNK) * DIM + d;

    #pragma unroll 4
    for (int i = 0; i < CHUNK; i++) {
        q[(size_t)i * DIM] = run;
        run += p[(size_t)i * DIM];
    }
    if (c == NCHUNK - 1) q[(size_t)CHUNK * DIM] = run;   // cs[SLEN]
}

// ---------------------------------------------------------------------------
// Kernel 3 (R2-proven, plain stores): one block per output row.
// grid = 16384, block = 192
// ---------------------------------------------------------------------------
__global__ __launch_bounds__(DIM4)
void span_kernel(const float* __restrict__ x,
                 const int* __restrict__ spans,
                 const int* __restrict__ pt_labels,
                 const float* __restrict__ wtab,
                 const float* __restrict__ ptab,
                 float* __restrict__ out) {
    const int bn = blockIdx.x;
    const int b  = bn >> 12;
    const int n  = bn & (NSPAN - 1);
    const int t  = threadIdx.x;

    const int i0 = spans[2 * n + 0];
    const int i1 = spans[2 * n + 1];
    const int width = i1 - i0 + 1;

    const int bins[16] = {0,1,2,3,4,5,7,8,9,10,15,16,31,32,63,64};
    int em = 0;
    #pragma unroll
    for (int i = 1; i < 16; i++) em = (width >= bins[i]) ? i : em;

    const int l0 = pt_labels[i0];
    const int l1 = pt_labels[i1];
    const float inv_w = 1.0f / (float)width;

    const float4 a  = ((const float4*)(g_cs + ((size_t)b * (SLEN + 1) + i0    ) * DIM))[t];
    const float4 bb = ((const float4*)(g_cs + ((size_t)b * (SLEN + 1) + i1 + 1) * DIM))[t];
    const float4 v0 = ((const float4*)(x    + ((size_t)b * SLEN + i0) * DIM))[t];
    const float4 v1 = ((const float4*)(x    + ((size_t)b * SLEN + i1) * DIM))[t];
    float* orow = out + (size_t)bn * OUTW;

    float4 m;
    m.x = (bb.x - a.x) * inv_w;
    m.y = (bb.y - a.y) * inv_w;
    m.z = (bb.z - a.z) * inv_w;
    m.w = (bb.w - a.w) * inv_w;

    ((float4*)(orow + OFF_MEAN))[t] = m;
    ((float4*)(orow + OFF_XS0 ))[t] = v0;
    ((float4*)(orow + OFF_XS1 ))[t] = v1;

    if (t < 5) {
        ((float4*)(orow + OFF_P0))[t] = ((const float4*)(ptab + l0 * 20))[t];
        ((float4*)(orow + OFF_P1))[t] = ((const float4*)(ptab + l1 * 20))[t];
        ((float4*)(orow + OFF_W ))[t] = ((const float4*)(wtab + em * 20))[t];
    }
}

// ---------------------------------------------------------------------------
extern "C" void kernel_launch(void* const* d_in, const int* in_sizes, int n_in,
                              void* d_out, int out_size) {
    const float* x      = (const float*)d_in[0];
    const int*   spans  = (const int*)d_in[1];
    const int*   labels = (const int*)d_in[2];
    const float* wtab   = (const float*)d_in[3];
    const float* ptab   = (const float*)d_in[4];
    float*       out    = (float*)d_out;

    chunksum_kernel  <<<NCBLK, DIM>>>(x);
    scan_write_kernel<<<NCBLK, DIM>>>(x);
    span_kernel      <<<NROWS, DIM4>>>(x, spans, labels, wtab, ptab, out);
}